// round 5
// baseline (speedup 1.0000x reference)
#include <cuda_runtime.h>
#include <math.h>

// SimDiff: right[f,i] = cos(x[f,i], x[f+1,i+1]),  i in [0, tpf-2]
//          down [f,i] = cos(x[f,i], x[f+1,i+W]),  i in [0, tpf-W-1]
// else -1.  Shapes fixed: frames=64, H=23, W=24, D=1152.

#define FRAMES 64
#define HEIGHT 23
#define WIDTH  24
#define TPF    (HEIGHT * WIDTH)   // 552
#define HID    1152
#define VALID  (FRAMES - 1)       // interval = 1
#define TOTAL  (FRAMES * TPF)     // 35328
#define EPS    1e-8f

#define ITERS2 (HID / 2 / 32)     // 18 float2 per lane per row
#define BURST  6                  // 6 iters x 3 streams = 18 LDG.64 per burst

__global__ void __launch_bounds__(256, 4)
simdiff_kernel(const float* __restrict__ x, float* __restrict__ out) {
    const int gwarp = (blockIdx.x * blockDim.x + threadIdx.x) >> 5;
    const int lane  = threadIdx.x & 31;
    if (gwarp >= TOTAL) return;

    const int f = gwarp / TPF;
    const int i = gwarp - f * TPF;

    const bool do_r = (f < VALID) && (i < TPF - 1);
    const bool do_d = (f < VALID) && (i < TPF - WIDTH);

    float right = -1.0f, down = -1.0f;

    if (do_r || do_d) {
        const float2* __restrict__ a =
            (const float2*)(x + (size_t)(f * TPF + i) * HID) + lane;
        // Guard invalid neighbors by aliasing to 'a' (no OOB, result unused).
        const float2* __restrict__ b = (do_r
            ? (const float2*)(x + (size_t)((f + 1) * TPF + i + 1) * HID)
            : (const float2*)(x + (size_t)(f * TPF + i) * HID)) + lane;
        const float2* __restrict__ c = (do_d
            ? (const float2*)(x + (size_t)((f + 1) * TPF + i + WIDTH) * HID)
            : (const float2*)(x + (size_t)(f * TPF + i) * HID)) + lane;

        float dab = 0.f, dac = 0.f, naa = 0.f, nbb = 0.f, ncc = 0.f;

        #pragma unroll
        for (int ch = 0; ch < ITERS2 / BURST; ++ch) {   // 3 bursts
            float2 av[BURST], bv[BURST], cv[BURST];
            #pragma unroll
            for (int u = 0; u < BURST; ++u) {
                const int k = (ch * BURST + u) * 32;
                av[u] = a[k]; bv[u] = b[k]; cv[u] = c[k];
            }
            #pragma unroll
            for (int u = 0; u < BURST; ++u) {
                dab = fmaf(av[u].x, bv[u].x, dab); dab = fmaf(av[u].y, bv[u].y, dab);
                dac = fmaf(av[u].x, cv[u].x, dac); dac = fmaf(av[u].y, cv[u].y, dac);
                naa = fmaf(av[u].x, av[u].x, naa); naa = fmaf(av[u].y, av[u].y, naa);
                nbb = fmaf(bv[u].x, bv[u].x, nbb); nbb = fmaf(bv[u].y, bv[u].y, nbb);
                ncc = fmaf(cv[u].x, cv[u].x, ncc); ncc = fmaf(cv[u].y, cv[u].y, ncc);
            }
        }

        // Warp tree-reduce 5 scalars.
        #pragma unroll
        for (int off = 16; off > 0; off >>= 1) {
            dab += __shfl_xor_sync(0xFFFFFFFFu, dab, off);
            dac += __shfl_xor_sync(0xFFFFFFFFu, dac, off);
            naa += __shfl_xor_sync(0xFFFFFFFFu, naa, off);
            nbb += __shfl_xor_sync(0xFFFFFFFFu, nbb, off);
            ncc += __shfl_xor_sync(0xFFFFFFFFu, ncc, off);
        }

        const float na = fmaxf(sqrtf(naa), EPS);
        if (do_r) {
            const float nb = fmaxf(sqrtf(nbb), EPS);
            right = dab / (na * nb);
        }
        if (do_d) {
            const float nc = fmaxf(sqrtf(ncc), EPS);
            down = dac / (na * nc);
        }
    }

    if (lane == 0) {
        out[gwarp]         = right;
        out[TOTAL + gwarp] = down;
    }
}

extern "C" void kernel_launch(void* const* d_in, const int* in_sizes, int n_in,
                              void* d_out, int out_size) {
    const float* x = (const float*)d_in[0];
    float* out = (float*)d_out;

    const int warps_per_block = 256 / 32;
    const int grid = (TOTAL + warps_per_block - 1) / warps_per_block; // 4416
    simdiff_kernel<<<grid, 256>>>(x, out);
}

// round 6
// speedup vs baseline: 1.0940x; 1.0940x over previous
#include <cuda_runtime.h>
#include <math.h>

// SimDiff: right[f,i] = cos(x[f,i], x[f+1,i+1]),  i in [0, tpf-2]
//          down [f,i] = cos(x[f,i], x[f+1,i+W]),  i in [0, tpf-W-1]
// else -1.  Shapes fixed: frames=64, H=23, W=24, D=1152.
//
// L2-traffic-reduction layout: each block owns 64 consecutive positions.
// Warp w processes positions p0 + 8k + w for k = 0..7, so the block's
// active window slides contiguously and row (f+1,j) — read as c by
// position j-24 and as b by position j-1 — gets its second read from L1.
// Single-use a-rows use __ldcg (L2-only) to avoid polluting L1.

#define FRAMES 64
#define HEIGHT 23
#define WIDTH  24
#define TPF    (HEIGHT * WIDTH)   // 552
#define HID    1152
#define VALID  (FRAMES - 1)       // interval = 1
#define TOTAL  (FRAMES * TPF)     // 35328
#define EPS    1e-8f

#define POS_PER_BLOCK 64
#define CHUNK 3                   // 3 iters x 3 streams = 9 float4 in flight

__global__ void __launch_bounds__(256, 2)
simdiff_kernel(const float* __restrict__ x, float* __restrict__ out) {
    const int warp = threadIdx.x >> 5;
    const int lane = threadIdx.x & 31;
    const int p0   = blockIdx.x * POS_PER_BLOCK;

    #pragma unroll 1
    for (int k = 0; k < 8; ++k) {
        const int pos = p0 + k * 8 + warp;   // global position
        const int f = pos / TPF;
        const int i = pos - f * TPF;

        const bool do_r = (f < VALID) && (i < TPF - 1);
        const bool do_d = (f < VALID) && (i < TPF - WIDTH);

        float right = -1.0f, down = -1.0f;

        if (do_r || do_d) {
            const float4* __restrict__ a =
                (const float4*)(x + (size_t)(f * TPF + i) * HID) + lane;
            // Guard invalid neighbors by aliasing to 'a' (no OOB, unused).
            const float4* __restrict__ b = (do_r
                ? (const float4*)(x + (size_t)((f + 1) * TPF + i + 1) * HID)
                : (const float4*)(x + (size_t)(f * TPF + i) * HID)) + lane;
            const float4* __restrict__ c = (do_d
                ? (const float4*)(x + (size_t)((f + 1) * TPF + i + WIDTH) * HID)
                : (const float4*)(x + (size_t)(f * TPF + i) * HID)) + lane;

            float dab = 0.f, dac = 0.f, naa = 0.f, nbb = 0.f, ncc = 0.f;

            #pragma unroll
            for (int ch = 0; ch < 3; ++ch) {      // 9 iters = 3 bursts of 3
                float4 av[CHUNK], bv[CHUNK], cv[CHUNK];
                #pragma unroll
                for (int u = 0; u < CHUNK; ++u) {
                    const int idx = (ch * CHUNK + u) * 32;
                    av[u] = __ldcg(a + idx);       // L2-only: single-use row
                    bv[u] = b[idx];                // default .ca: reusable
                    cv[u] = c[idx];                // default .ca: reusable
                }
                #pragma unroll
                for (int u = 0; u < CHUNK; ++u) {
                    dab = fmaf(av[u].x, bv[u].x, dab); dab = fmaf(av[u].y, bv[u].y, dab);
                    dab = fmaf(av[u].z, bv[u].z, dab); dab = fmaf(av[u].w, bv[u].w, dab);
                    dac = fmaf(av[u].x, cv[u].x, dac); dac = fmaf(av[u].y, cv[u].y, dac);
                    dac = fmaf(av[u].z, cv[u].z, dac); dac = fmaf(av[u].w, cv[u].w, dac);
                    naa = fmaf(av[u].x, av[u].x, naa); naa = fmaf(av[u].y, av[u].y, naa);
                    naa = fmaf(av[u].z, av[u].z, naa); naa = fmaf(av[u].w, av[u].w, naa);
                    nbb = fmaf(bv[u].x, bv[u].x, nbb); nbb = fmaf(bv[u].y, bv[u].y, nbb);
                    nbb = fmaf(bv[u].z, bv[u].z, nbb); nbb = fmaf(bv[u].w, bv[u].w, nbb);
                    ncc = fmaf(cv[u].x, cv[u].x, ncc); ncc = fmaf(cv[u].y, cv[u].y, ncc);
                    ncc = fmaf(cv[u].z, cv[u].z, ncc); ncc = fmaf(cv[u].w, cv[u].w, ncc);
                }
            }

            // Warp tree-reduce 5 scalars.
            #pragma unroll
            for (int off = 16; off > 0; off >>= 1) {
                dab += __shfl_xor_sync(0xFFFFFFFFu, dab, off);
                dac += __shfl_xor_sync(0xFFFFFFFFu, dac, off);
                naa += __shfl_xor_sync(0xFFFFFFFFu, naa, off);
                nbb += __shfl_xor_sync(0xFFFFFFFFu, nbb, off);
                ncc += __shfl_xor_sync(0xFFFFFFFFu, ncc, off);
            }

            const float na = fmaxf(sqrtf(naa), EPS);
            if (do_r) {
                const float nb = fmaxf(sqrtf(nbb), EPS);
                right = dab / (na * nb);
            }
            if (do_d) {
                const float nc = fmaxf(sqrtf(ncc), EPS);
                down = dac / (na * nc);
            }
        }

        if (lane == 0) {
            out[pos]         = right;
            out[TOTAL + pos] = down;
        }
    }
}

extern "C" void kernel_launch(void* const* d_in, const int* in_sizes, int n_in,
                              void* d_out, int out_size) {
    const float* x = (const float*)d_in[0];
    float* out = (float*)d_out;

    const int grid = TOTAL / POS_PER_BLOCK;  // 552 blocks, 64 positions each
    simdiff_kernel<<<grid, 256>>>(x, out);
}

// round 7
// speedup vs baseline: 1.2889x; 1.1782x over previous
#include <cuda_runtime.h>
#include <math.h>

// SimDiff with shared-target chains.
//   right[f,i] = cos(x[f,i], x[f+1,i+1]),  valid i <= 550
//   down [f,i] = cos(x[f,i], x[f+1,i+24]), valid i <= 527
// Key identity: down(f,i) and right(f,i+23) share target row x[f+1,i+24].
// A warp walks positions i, i+23, i+46, ... carrying the shared target row
// in registers: 2k+1 row loads for 2k outputs (ratio 2.125 at k=8) vs 3.0
// for the position-centric kernel. Frames 0..62 fully covered by chains;
// frame 63 outputs are all -1 (fill kernel).

#define FRAMES 64
#define WIDTH  24
#define TPF    552
#define HID    1152
#define TOTAL  (FRAMES * TPF)     // 35328
#define EPS    1e-8f

#define SEG    8                  // positions per warp segment
#define CHPF   23                 // chains per frame (i mod 23)
#define SPC    3                  // segments per chain (24 positions / 8)
#define WPF    (CHPF * SPC)       // 69 warps per frame
#define NWARPS ((FRAMES - 1) * WPF)  // 4347 compute warps
#define ROWQ   (HID / 4)          // 288 float4 per row

__global__ void __launch_bounds__(256, 2)
chain_kernel(const float* __restrict__ x, float* __restrict__ out) {
    const int w    = (blockIdx.x * blockDim.x + threadIdx.x) >> 5;
    const int lane = threadIdx.x & 31;
    if (w >= NWARPS) return;

    const int f  = w / WPF;
    const int r  = w - f * WPF;
    const int c  = r / SPC;           // chain id 0..22
    const int s  = r - c * SPC;       // segment 0..2
    const int col0 = c + CHPF * (SEG * s);   // first position col (<= 390)

    const float4* __restrict__ base = (const float4*)x;

    // Ping-pong target rows + their reduced norms.
    float4 t[2][9];
    float  ntt[2];

    // Preload t_0 = row (f+1, col0+1)  (col0+1 <= 391, always in range).
    {
        const float4* tp = base + (size_t)((f + 1) * TPF + col0 + 1) * ROWQ + lane;
        #pragma unroll
        for (int u = 0; u < 9; ++u) t[0][u] = tp[u * 32];
        float nt = 0.f;
        #pragma unroll
        for (int u = 0; u < 9; ++u) {
            nt = fmaf(t[0][u].x, t[0][u].x, nt); nt = fmaf(t[0][u].y, t[0][u].y, nt);
            nt = fmaf(t[0][u].z, t[0][u].z, nt); nt = fmaf(t[0][u].w, t[0][u].w, nt);
        }
        #pragma unroll
        for (int off = 16; off; off >>= 1) nt += __shfl_xor_sync(~0u, nt, off);
        ntt[0] = nt;
    }

    #pragma unroll
    for (int m = 0; m < SEG; ++m) {
        const int colm = col0 + CHPF * m;
        const int cur = m & 1, nxt = cur ^ 1;
        const bool vr = (colm <= TPF - 2);          // right valid
        const bool vd = (colm <= TPF - WIDTH - 1);  // down valid
        // t_{m+1} = row (f+1, colm+24); clamp col (masked when invalid).
        const int coln = min(colm + WIDTH, TPF - 1);

        const float4* ap = base + (size_t)(f * TPF + colm) * ROWQ + lane;
        const float4* tp = base + (size_t)((f + 1) * TPF + coln) * ROWQ + lane;

        // Load next target row (9 independent LDG.128 in flight).
        #pragma unroll
        for (int u = 0; u < 9; ++u) t[nxt][u] = tp[u * 32];

        float dr = 0.f, dd = 0.f, na = 0.f, nt = 0.f;

        // a-row in bursts of 3, consumed against t[cur] (right) and t[nxt] (down).
        #pragma unroll
        for (int ch = 0; ch < 3; ++ch) {
            float4 av[3];
            #pragma unroll
            for (int u = 0; u < 3; ++u) av[u] = ap[(ch * 3 + u) * 32];
            #pragma unroll
            for (int u = 0; u < 3; ++u) {
                const int k = ch * 3 + u;
                const float4 tc = t[cur][k];
                const float4 tn = t[nxt][k];
                dr = fmaf(av[u].x, tc.x, dr); dr = fmaf(av[u].y, tc.y, dr);
                dr = fmaf(av[u].z, tc.z, dr); dr = fmaf(av[u].w, tc.w, dr);
                dd = fmaf(av[u].x, tn.x, dd); dd = fmaf(av[u].y, tn.y, dd);
                dd = fmaf(av[u].z, tn.z, dd); dd = fmaf(av[u].w, tn.w, dd);
                na = fmaf(av[u].x, av[u].x, na); na = fmaf(av[u].y, av[u].y, na);
                na = fmaf(av[u].z, av[u].z, na); na = fmaf(av[u].w, av[u].w, na);
            }
        }
        #pragma unroll
        for (int u = 0; u < 9; ++u) {
            nt = fmaf(t[nxt][u].x, t[nxt][u].x, nt); nt = fmaf(t[nxt][u].y, t[nxt][u].y, nt);
            nt = fmaf(t[nxt][u].z, t[nxt][u].z, nt); nt = fmaf(t[nxt][u].w, t[nxt][u].w, nt);
        }

        #pragma unroll
        for (int off = 16; off; off >>= 1) {
            dr += __shfl_xor_sync(~0u, dr, off);
            dd += __shfl_xor_sync(~0u, dd, off);
            na += __shfl_xor_sync(~0u, na, off);
            nt += __shfl_xor_sync(~0u, nt, off);
        }
        ntt[nxt] = nt;

        if (lane == 0) {
            const float nA = fmaxf(sqrtf(na), EPS);
            float rr = -1.f, dn = -1.f;
            if (vr) rr = dr / (nA * fmaxf(sqrtf(ntt[cur]), EPS));
            if (vd) dn = dd / (nA * fmaxf(sqrtf(ntt[nxt]), EPS));
            out[f * TPF + colm]         = rr;
            out[TOTAL + f * TPF + colm] = dn;
        }
    }
}

// Frame 63 (last frame) outputs are all -1 — chains only cover f <= 62.
__global__ void fill_last_frame(float* __restrict__ out) {
    const int idx = blockIdx.x * blockDim.x + threadIdx.x;
    if (idx < TPF) {
        out[(FRAMES - 1) * TPF + idx]         = -1.0f;
        out[TOTAL + (FRAMES - 1) * TPF + idx] = -1.0f;
    }
}

extern "C" void kernel_launch(void* const* d_in, const int* in_sizes, int n_in,
                              void* d_out, int out_size) {
    const float* x = (const float*)d_in[0];
    float* out = (float*)d_out;

    fill_last_frame<<<(TPF + 255) / 256, 256>>>(out);

    const int warps_per_block = 256 / 32;
    const int grid = (NWARPS + warps_per_block - 1) / warps_per_block; // 544
    chain_kernel<<<grid, 256>>>(x, out);
}